// round 16
// baseline (speedup 1.0000x reference)
#include <cuda_runtime.h>
#include <cstdint>

// Problem shape (fixed by the reference): B=4, N=M=8192, D=3, fp32.
// Exact NN via uniform grid (G=16) + pruned cube expansion.
// Cell-sorted queries, warp-interleaved CTA mapping, unrolled scans.
#define BATCH   4
#define NPTS    8192
#define G       16
#define NC      (G * G * G)            // 4096 cells per grid
#define NGRIDS  (2 * BATCH)            // 8: [0..3]=y content per batch, [4..7]=x content
#define TOTQ    (2 * BATCH * NPTS)     // 65536 queries
#define GS      1.6f                   // G / 10
#define H       0.625f                 // 10 / G (exact in fp32)
#define LOV     (-5.0f)
#define EPS     1e-3f
#define QCTAS   256
#define QTHREADS 256
#define SUMA_CTAS 64

// Static scratch (zero-initialized at load; g_cnt re-zeroed by sumA each replay).
__device__ int    g_cnt[NGRIDS * NC];
__device__ int    g_start[NGRIDS * NC];
__device__ int    g_end[NGRIDS * NC];
__device__ int    g_cursor[NGRIDS * NC];
__device__ float4 g_pts[NGRIDS * NPTS];   // .w carries original within-batch index
__device__ float  g_res[TOTQ];
__device__ float  g_part[SUMA_CTAS];

__device__ __forceinline__ int cellco(float v) {
    int c = (int)((v - LOV) * GS);
    return min(max(c, 0), G - 1);
}

// ---------------- 1. count points per cell ----------------
__global__ void count_kernel(const float* __restrict__ x, const float* __restrict__ y) {
    int tid = blockIdx.x * blockDim.x + threadIdx.x;   // 65536
    int i = tid & (NPTS - 1);
    int b = (tid >> 13) & 3;
    int s = tid >> 15;                                  // 0: content y, 1: content x
    const float* src = s ? x : y;
    const float* p = src + ((size_t)b * NPTS + i) * 3;
    int cell = (cellco(p[2]) * G + cellco(p[1])) * G + cellco(p[0]);
    atomicAdd(&g_cnt[(s * BATCH + b) * NC + cell], 1);
}

// ---------------- 2. per-grid scan: starts, ends, cursors (one block per grid) ----------------
__global__ void scan_kernel() {
    __shared__ int sm[1024];
    int t = threadIdx.x;
    int base = blockIdx.x * NC + t * 4;
    int c0 = g_cnt[base], c1 = g_cnt[base + 1], c2 = g_cnt[base + 2], c3 = g_cnt[base + 3];
    int tot = c0 + c1 + c2 + c3;
    sm[t] = tot;
    __syncthreads();
    for (int off = 1; off < 1024; off <<= 1) {
        int v = (t >= off) ? sm[t - off] : 0;
        __syncthreads();
        sm[t] += v;
        __syncthreads();
    }
    int e = sm[t] - tot;
    int s0 = e, s1 = e + c0, s2 = s1 + c1, s3 = s2 + c2;
    g_start[base] = s0;   g_end[base] = s1;        g_cursor[base] = s0;
    g_start[base+1] = s1; g_end[base+1] = s2;      g_cursor[base+1] = s1;
    g_start[base+2] = s2; g_end[base+2] = s3;      g_cursor[base+2] = s2;
    g_start[base+3] = s3; g_end[base+3] = s3 + c3; g_cursor[base+3] = s3;
}

// ---------------- 3. scatter points (with original index) into CSR order ----------------
__global__ void scatter_kernel(const float* __restrict__ x, const float* __restrict__ y) {
    int tid = blockIdx.x * blockDim.x + threadIdx.x;
    int i = tid & (NPTS - 1);
    int b = (tid >> 13) & 3;
    int s = tid >> 15;
    const float* src = s ? x : y;
    const float* p = src + ((size_t)b * NPTS + i) * 3;
    float p0 = p[0], p1 = p[1], p2 = p[2];
    int cell = (cellco(p2) * G + cellco(p1)) * G + cellco(p0);
    int g = s * BATCH + b;
    int pos = atomicAdd(&g_cursor[g * NC + cell], 1);
    g_pts[g * NPTS + pos] = make_float4(p0, p1, p2, __int_as_float(i));
}

// ---------------- 4. query: sorted order, warp-interleaved mapping ----------------
__global__ void __launch_bounds__(QTHREADS)
query_kernel() {
    // warp slot (cta, wlocal) -> sorted-query warp W = wlocal * QCTAS + cta.
    // Keeps 32 consecutive sorted queries per warp (convergence) while giving
    // every CTA a uniform sample of heavy/light regions (no correlated tail).
    int wlocal = threadIdx.x >> 5;
    int lane   = threadIdx.x & 31;
    int W = wlocal * QCTAS + blockIdx.x;
    int tid = W * 32 + lane;            // 0..65535 over sorted queries

    int k = tid & (NPTS - 1);           // position within the scattered query array
    int b = (tid >> 13) & 3;
    int s = tid >> 15;                  // 0: x queries -> y grid; 1: y queries -> x grid
    int qg = s ? b : (BATCH + b);       // grid holding the QUERY points (cell-sorted)
    int g  = s ? (BATCH + b) : b;       // grid we SEARCH

    float4 qv = g_pts[qg * NPTS + k];
    float q0 = qv.x, q1 = qv.y, q2 = qv.z;
    int qi = __float_as_int(qv.w);      // original within-batch index

    const int*    st = g_start + g * NC;
    const int*    en = g_end   + g * NC;
    const float4* pp = g_pts   + g * NPTS;

    int cx = cellco(q0), cy = cellco(q1), cz = cellco(q2);
    float best = 3.0e38f;

    // center cell first (establishes a tight best for pruning)
    {
        int c = (cz * G + cy) * G + cx;
        int j0 = st[c], j1 = en[c];
#pragma unroll 4
        for (int j = j0; j < j1; j++) {
            float4 p = pp[j];
            float d0 = q0 - p.x, d1 = q1 - p.y, d2 = q2 - p.z;
            best = fminf(best, fmaf(d0, d0, fmaf(d1, d1, d2 * d2)));
        }
    }

    for (int r = 1; ; r++) {
        int zl = max(cz - r, 0), zh = min(cz + r, G - 1);
        int yl = max(cy - r, 0), yh = min(cy + r, G - 1);
        for (int z = zl; z <= zh; z++) {
            float dzd = 0.0f;
            if (z < cz)      dzd = q2 - (LOV + (float)(z + 1) * H);
            else if (z > cz) dzd = (LOV + (float)z * H) - q2;
            dzd = fmaxf(dzd - EPS, 0.0f);
            float dz2 = dzd * dzd;
            if (dz2 >= best) continue;
            for (int yy = yl; yy <= yh; yy++) {
                float dyd = 0.0f;
                if (yy < cy)      dyd = q1 - (LOV + (float)(yy + 1) * H);
                else if (yy > cy) dyd = (LOV + (float)yy * H) - q1;
                dyd = fmaxf(dyd - EPS, 0.0f);
                float rb = fmaf(dyd, dyd, dz2);
                if (rb >= best) continue;
                float rad = sqrtf(best - rb);
                int xl = max(cellco(q0 - rad), max(cx - r, 0));
                int xh = min(cellco(q0 + rad), min(cx + r, G - 1));
                if (xl > xh) continue;
                int rowb = (z * G + yy) * G;
                int j0 = st[rowb + xl], j1 = en[rowb + xh];
#pragma unroll 4
                for (int j = j0; j < j1; j++) {
                    float4 p = pp[j];
                    float d0 = q0 - p.x, d1 = q1 - p.y, d2 = q2 - p.z;
                    best = fminf(best, fmaf(d0, d0, fmaf(d1, d1, d2 * d2)));
                }
            }
        }
        // unscanned cells (Chebyshev >= r+1) hold points at distance >= r*H (fp slack)
        float bnd = (float)r * H - 0.01f;
        if (best <= bnd * bnd || r >= G - 1) break;
    }

    // deterministic slot: original query identity, independent of scatter order
    g_res[(s * BATCH + b) * NPTS + qi] = fmaxf(best, 0.0f);
}

// ---------------- 5a. 64-CTA deterministic partial sums (+ re-zero counts) ----------------
__global__ void sumA_kernel() {
    __shared__ float red[256];
    const float4* gp = (const float4*)g_res;
    float4 v = gp[blockIdx.x * 256 + threadIdx.x];
    float ss = (v.x + v.y) + (v.z + v.w);
    ((int2*)g_cnt)[blockIdx.x * 256 + threadIdx.x] = make_int2(0, 0);  // reset counts
    red[threadIdx.x] = ss;
    __syncthreads();
    for (int kk = 128; kk > 0; kk >>= 1) {
        if (threadIdx.x < kk) red[threadIdx.x] += red[threadIdx.x + kk];
        __syncthreads();
    }
    if (threadIdx.x == 0) g_part[blockIdx.x] = red[0];
}

// ---------------- 5b. combine partials + scale ----------------
__global__ void sumB_kernel(float* __restrict__ out) {
    __shared__ float red[SUMA_CTAS];
    red[threadIdx.x] = g_part[threadIdx.x];
    __syncthreads();
    for (int kk = SUMA_CTAS / 2; kk > 0; kk >>= 1) {
        if (threadIdx.x < kk) red[threadIdx.x] += red[threadIdx.x + kk];
        __syncthreads();
    }
    if (threadIdx.x == 0)
        out[0] = red[0] * (1.0f / (float)(BATCH * NPTS));
}

extern "C" void kernel_launch(void* const* d_in, const int* in_sizes, int n_in,
                              void* d_out, int out_size) {
    const float* x = (const float*)d_in[0];
    const float* y = (const float*)d_in[1];
    float* out = (float*)d_out;
    (void)in_sizes; (void)n_in; (void)out_size;

    count_kernel<<<TOTQ / 256, 256>>>(x, y);
    scan_kernel<<<NGRIDS, 1024>>>();
    scatter_kernel<<<TOTQ / 256, 256>>>(x, y);
    query_kernel<<<QCTAS, QTHREADS>>>();
    sumA_kernel<<<SUMA_CTAS, 256>>>();
    sumB_kernel<<<1, SUMA_CTAS>>>(out);
}

// round 17
// speedup vs baseline: 1.1423x; 1.1423x over previous
#include <cuda_runtime.h>
#include <cstdint>

// Problem shape (fixed by the reference): B=4, N=M=8192, D=3, fp32.
// Exact NN via uniform grid (G=16) + pruned cube expansion.
// Cell-sorted queries (R12 structure); fused int2 CSR ranges; fused final sum.
#define BATCH   4
#define NPTS    8192
#define G       16
#define NC      (G * G * G)            // 4096 cells per grid
#define NGRIDS  (2 * BATCH)            // 8: [0..3]=y content per batch, [4..7]=x content
#define TOTQ    (2 * BATCH * NPTS)     // 65536 queries
#define GS      1.6f                   // G / 10
#define H       0.625f                 // 10 / G (exact in fp32)
#define LOV     (-5.0f)
#define EPS     1e-3f
#define SUMA_CTAS 64

// Static scratch (zero-initialized at load; g_cnt re-zeroed by sum kernel each replay).
__device__ int    g_cnt[NGRIDS * NC];
__device__ int2   g_se[NGRIDS * NC];      // fused (start, end) per cell
__device__ int    g_cursor[NGRIDS * NC];
__device__ float4 g_pts[NGRIDS * NPTS];   // .w carries original within-batch index
__device__ float  g_res[TOTQ];
__device__ float  g_part[SUMA_CTAS];
__device__ int    g_ticket;               // sum stage last-block ticket

__device__ __forceinline__ int cellco(float v) {
    int c = (int)((v - LOV) * GS);
    return min(max(c, 0), G - 1);
}

// ---------------- 1. count points per cell ----------------
__global__ void count_kernel(const float* __restrict__ x, const float* __restrict__ y) {
    int tid = blockIdx.x * blockDim.x + threadIdx.x;   // 65536
    int i = tid & (NPTS - 1);
    int b = (tid >> 13) & 3;
    int s = tid >> 15;                                  // 0: content y, 1: content x
    const float* src = s ? x : y;
    const float* p = src + ((size_t)b * NPTS + i) * 3;
    int cell = (cellco(p[2]) * G + cellco(p[1])) * G + cellco(p[0]);
    atomicAdd(&g_cnt[(s * BATCH + b) * NC + cell], 1);
}

// ---------------- 2. per-grid scan: fused (start,end) + cursors (one block per grid) ----------------
__global__ void scan_kernel() {
    __shared__ int sm[1024];
    int t = threadIdx.x;
    int base = blockIdx.x * NC + t * 4;
    int c0 = g_cnt[base], c1 = g_cnt[base + 1], c2 = g_cnt[base + 2], c3 = g_cnt[base + 3];
    int tot = c0 + c1 + c2 + c3;
    sm[t] = tot;
    __syncthreads();
    for (int off = 1; off < 1024; off <<= 1) {
        int v = (t >= off) ? sm[t - off] : 0;
        __syncthreads();
        sm[t] += v;
        __syncthreads();
    }
    int e = sm[t] - tot;
    int s0 = e, s1 = e + c0, s2 = s1 + c1, s3 = s2 + c2, s4 = s3 + c3;
    g_se[base]     = make_int2(s0, s1);  g_cursor[base]     = s0;
    g_se[base + 1] = make_int2(s1, s2);  g_cursor[base + 1] = s1;
    g_se[base + 2] = make_int2(s2, s3);  g_cursor[base + 2] = s2;
    g_se[base + 3] = make_int2(s3, s4);  g_cursor[base + 3] = s3;
}

// ---------------- 3. scatter points (with original index) into CSR order ----------------
__global__ void scatter_kernel(const float* __restrict__ x, const float* __restrict__ y) {
    int tid = blockIdx.x * blockDim.x + threadIdx.x;
    int i = tid & (NPTS - 1);
    int b = (tid >> 13) & 3;
    int s = tid >> 15;
    const float* src = s ? x : y;
    const float* p = src + ((size_t)b * NPTS + i) * 3;
    float p0 = p[0], p1 = p[1], p2 = p[2];
    int cell = (cellco(p2) * G + cellco(p1)) * G + cellco(p0);
    int g = s * BATCH + b;
    int pos = atomicAdd(&g_cursor[g * NC + cell], 1);
    g_pts[g * NPTS + pos] = make_float4(p0, p1, p2, __int_as_float(i));
}

// ---------------- 4. query: cell-sorted order, exact pruned cube expansion ----------------
__global__ void __launch_bounds__(256)
query_kernel() {
    int tid = blockIdx.x * blockDim.x + threadIdx.x;   // 65536
    int k = tid & (NPTS - 1);           // position within the scattered query array
    int b = (tid >> 13) & 3;
    int s = tid >> 15;                  // 0: x queries -> y grid; 1: y queries -> x grid
    int qg = s ? b : (BATCH + b);       // grid holding the QUERY points (cell-sorted)
    int g  = s ? (BATCH + b) : b;       // grid we SEARCH

    float4 qv = g_pts[qg * NPTS + k];
    float q0 = qv.x, q1 = qv.y, q2 = qv.z;
    int qi = __float_as_int(qv.w);      // original within-batch index

    const int2*   se = g_se  + g * NC;
    const float4* pp = g_pts + g * NPTS;

    int cx = cellco(q0), cy = cellco(q1), cz = cellco(q2);
    float best = 3.0e38f;

    // center cell first (single int2 range load; establishes a tight best)
    {
        int2 r0 = se[(cz * G + cy) * G + cx];
        for (int j = r0.x; j < r0.y; j++) {
            float4 p = pp[j];
            float d0 = q0 - p.x, d1 = q1 - p.y, d2 = q2 - p.z;
            best = fminf(best, fmaf(d0, d0, fmaf(d1, d1, d2 * d2)));
        }
    }

    for (int r = 1; ; r++) {
        int zl = max(cz - r, 0), zh = min(cz + r, G - 1);
        int yl = max(cy - r, 0), yh = min(cy + r, G - 1);
        for (int z = zl; z <= zh; z++) {
            float dzd = 0.0f;
            if (z < cz)      dzd = q2 - (LOV + (float)(z + 1) * H);
            else if (z > cz) dzd = (LOV + (float)z * H) - q2;
            dzd = fmaxf(dzd - EPS, 0.0f);
            float dz2 = dzd * dzd;
            if (dz2 >= best) continue;
            for (int yy = yl; yy <= yh; yy++) {
                float dyd = 0.0f;
                if (yy < cy)      dyd = q1 - (LOV + (float)(yy + 1) * H);
                else if (yy > cy) dyd = (LOV + (float)yy * H) - q1;
                dyd = fmaxf(dyd - EPS, 0.0f);
                float rb = fmaf(dyd, dyd, dz2);
                if (rb >= best) continue;
                float rad = sqrtf(best - rb);
                int xl = max(cellco(q0 - rad), max(cx - r, 0));
                int xh = min(cellco(q0 + rad), min(cx + r, G - 1));
                if (xl > xh) continue;
                int rowb = (z * G + yy) * G;
                // fused ranges: one load when xl==xh, two independent otherwise
                int j0, j1;
                if (xl == xh) {
                    int2 rr = se[rowb + xl];
                    j0 = rr.x; j1 = rr.y;
                } else {
                    j0 = se[rowb + xl].x;
                    j1 = se[rowb + xh].y;
                }
                for (int j = j0; j < j1; j++) {
                    float4 p = pp[j];
                    float d0 = q0 - p.x, d1 = q1 - p.y, d2 = q2 - p.z;
                    best = fminf(best, fmaf(d0, d0, fmaf(d1, d1, d2 * d2)));
                }
            }
        }
        // unscanned cells (Chebyshev >= r+1) hold points at distance >= r*H (fp slack)
        float bnd = (float)r * H - 0.01f;
        if (best <= bnd * bnd || r >= G - 1) break;
    }

    // deterministic slot: original query identity, independent of scatter order
    g_res[(s * BATCH + b) * NPTS + qi] = fmaxf(best, 0.0f);
}

// ---------------- 5. fused sum: partials + last-block final reduce ----------------
__global__ void sum_kernel(float* __restrict__ out) {
    __shared__ float red[256];
    const float4* gp = (const float4*)g_res;
    float4 v = gp[blockIdx.x * 256 + threadIdx.x];
    float ss = (v.x + v.y) + (v.z + v.w);
    ((int2*)g_cnt)[blockIdx.x * 256 + threadIdx.x] = make_int2(0, 0);  // reset counts
    red[threadIdx.x] = ss;
    __syncthreads();
    for (int kk = 128; kk > 0; kk >>= 1) {
        if (threadIdx.x < kk) red[threadIdx.x] += red[threadIdx.x + kk];
        __syncthreads();
    }
    __shared__ int s_last;
    if (threadIdx.x == 0) {
        g_part[blockIdx.x] = red[0];
        __threadfence();
        int t = atomicAdd(&g_ticket, 1);
        s_last = (t == SUMA_CTAS - 1) ? 1 : 0;
    }
    __syncthreads();
    if (s_last && threadIdx.x == 0) {
        // fixed-order final reduce: deterministic
        float tot = 0.0f;
        for (int i = 0; i < SUMA_CTAS; i++) tot += g_part[i];
        out[0] = tot * (1.0f / (float)(BATCH * NPTS));
        g_ticket = 0;                    // reset for next replay
    }
}

extern "C" void kernel_launch(void* const* d_in, const int* in_sizes, int n_in,
                              void* d_out, int out_size) {
    const float* x = (const float*)d_in[0];
    const float* y = (const float*)d_in[1];
    float* out = (float*)d_out;
    (void)in_sizes; (void)n_in; (void)out_size;

    count_kernel<<<TOTQ / 256, 256>>>(x, y);
    scan_kernel<<<NGRIDS, 1024>>>();
    scatter_kernel<<<TOTQ / 256, 256>>>(x, y);
    query_kernel<<<TOTQ / 256, 256>>>();
    sum_kernel<<<SUMA_CTAS, 256>>>(out);
}